// round 17
// baseline (speedup 1.0000x reference)
#include <cuda_runtime.h>
#include <cuda_fp16.h>
#include <cstdint>

#define NUM_USERS 50000
#define NUM_ITEMS 50000
#define N_NODES   100000
#define HIDDEN    128
#define N_EDGES   1600000

#define CAP       96        // per-node edge capacity (max deg ~35)

#define GEMM_TILES 782      // ceil(100000/128)
#define FUSE_NBLK  148      // 1 block/SM (160 KB smem)

// smem map (dynamic, bytes)
#define SB_B    0           // 4 x 16 KB resident weights
#define SB_AGG  65536       // 2 tile-slots x 2 chunk-stages x 16 KB
#define SB_X    131072      // 2 x 16 KB x-half double buffer
#define FUSE_SMEM (160 * 1024)

// ---------------------------------------------------------------------------
// Scratch (static device globals; no runtime allocation)
// ---------------------------------------------------------------------------
__device__ __half g_xh0[(size_t)N_NODES * HIDDEN];
__device__ __half g_xh1[(size_t)N_NODES * HIDDEN];
__device__ __half g_wh[4 * HIDDEN * HIDDEN];         // Wl0,Wl1,Wr0,Wr1
__device__ int    g_cnt[N_NODES];
__device__ int    g_col[(size_t)N_NODES * CAP];

// ---------------------------------------------------------------------------
// zero cnt
// ---------------------------------------------------------------------------
#define ZC_BLOCKS ((N_NODES + 255) / 256)

__global__ void zero_cnt_kernel() {
    int i = blockIdx.x * blockDim.x + threadIdx.x;
    if (i < N_NODES) g_cnt[i] = 0;
}

// ---------------------------------------------------------------------------
// fat prologue: convert x0 | convert W | bucket-fill
// ---------------------------------------------------------------------------
__device__ __forceinline__ uint2 f4_to_h4(float4 v) {
    __half2 a = __float22half2_rn(make_float2(v.x, v.y));
    __half2 b = __float22half2_rn(make_float2(v.z, v.w));
    uint2 r;
    r.x = *(uint32_t*)&a;
    r.y = *(uint32_t*)&b;
    return r;
}

#define CVX_BLOCKS 6250
#define CVW_BLOCKS 64
#define F4_BLOCKS  1563

__global__ void fat_prologue_kernel(const float* __restrict__ ue,
                                    const float* __restrict__ ie,
                                    const float* __restrict__ Wl,
                                    const float* __restrict__ Wr,
                                    const int* __restrict__ ei) {
    int bid = blockIdx.x;
    if (bid < CVX_BLOCKS) {
        int i = bid * 256 + threadIdx.x;
        const int half8 = NUM_USERS * HIDDEN / 8;
        const float4* src;
        if (i < half8) src = (const float4*)ue + 2 * i;
        else           src = (const float4*)ie + 2 * (i - half8);
        uint2 lo = f4_to_h4(src[0]);
        uint2 hi = f4_to_h4(src[1]);
        ((uint4*)g_xh0)[i] = make_uint4(lo.x, lo.y, hi.x, hi.y);
    } else if (bid < CVX_BLOCKS + CVW_BLOCKS) {
        int i = (bid - CVX_BLOCKS) * 256 + threadIdx.x;
        const int wq = 2 * HIDDEN * HIDDEN / 4;
        if (i < wq)
            ((uint2*)g_wh)[i] = f4_to_h4(((const float4*)Wl)[i]);
        else
            ((uint2*)g_wh)[i] = f4_to_h4(((const float4*)Wr)[i - wq]);
    } else {
        int e = ((bid - CVX_BLOCKS - CVW_BLOCKS) * 256 + threadIdx.x) * 4;
        if (e + 3 < N_EDGES) {
            int4 s = *(const int4*)(ei + e);
            int4 d = *(const int4*)(ei + N_EDGES + e);
            g_col[(size_t)d.x * CAP + atomicAdd(&g_cnt[d.x], 1)] = s.x;
            g_col[(size_t)d.y * CAP + atomicAdd(&g_cnt[d.y], 1)] = s.y;
            g_col[(size_t)d.z * CAP + atomicAdd(&g_cnt[d.z], 1)] = s.z;
            g_col[(size_t)d.w * CAP + atomicAdd(&g_cnt[d.w], 1)] = s.w;
        } else {
            for (; e < N_EDGES; e++) {
                int src = __ldg(ei + e);
                int dst = __ldg(ei + N_EDGES + e);
                g_col[(size_t)dst * CAP + atomicAdd(&g_cnt[dst], 1)] = src;
            }
        }
    }
}

// ---------------------------------------------------------------------------
// helpers
// ---------------------------------------------------------------------------
__device__ __forceinline__ void mma_f16(float* d,
                                        uint32_t a0, uint32_t a1,
                                        uint32_t a2, uint32_t a3,
                                        uint32_t b0, uint32_t b1) {
    asm("mma.sync.aligned.m16n8k16.row.col.f32.f16.f16.f32 "
        "{%0,%1,%2,%3}, {%4,%5,%6,%7}, {%8,%9}, {%0,%1,%2,%3};"
        : "+f"(d[0]), "+f"(d[1]), "+f"(d[2]), "+f"(d[3])
        : "r"(a0), "r"(a1), "r"(a2), "r"(a3), "r"(b0), "r"(b1));
}

__device__ __forceinline__ void ldsm_x4(uint32_t* r, uint32_t addr) {
    asm volatile("ldmatrix.sync.aligned.m8n8.x4.shared.b16 "
                 "{%0,%1,%2,%3}, [%4];"
                 : "=r"(r[0]), "=r"(r[1]), "=r"(r[2]), "=r"(r[3])
                 : "r"(addr));
}

__device__ __forceinline__ void cp16(uint32_t dst, const void* src,
                                     uint32_t srcsize) {
    asm volatile("cp.async.cg.shared.global [%0], [%1], 16, %2;"
                 :: "r"(dst), "l"(src), "r"(srcsize) : "memory");
}

__device__ __forceinline__ uint32_t smem_u32(const void* p) {
    uint32_t a;
    asm("{ .reg .u64 t; cvta.to.shared.u64 t, %1; cvt.u32.u64 %0, t; }"
        : "=r"(a) : "l"(p));
    return a;
}

__device__ __forceinline__ void mbar_init(uint32_t a, uint32_t cnt) {
    asm volatile("mbarrier.init.shared.b64 [%0], %1;"
                 :: "r"(a), "r"(cnt) : "memory");
}

__device__ __forceinline__ void mbar_arrive(uint32_t a) {
    asm volatile("mbarrier.arrive.shared.b64 _, [%0];"
                 :: "r"(a) : "memory");
}

__device__ __forceinline__ void mbar_wait(uint32_t a, uint32_t parity) {
    asm volatile(
        "{ .reg .pred P; "
        "WL%=: mbarrier.try_wait.parity.acquire.cta.shared::cta.b64 P, [%0], %1; "
        "@P bra WD%=; bra WL%=; WD%=: }"
        :: "r"(a), "r"(parity) : "memory");
}

__device__ __forceinline__ void acc8(float* a, uint4 v) {
    float2 f0 = __half22float2(*(__half2*)&v.x);
    float2 f1 = __half22float2(*(__half2*)&v.y);
    float2 f2 = __half22float2(*(__half2*)&v.z);
    float2 f3 = __half22float2(*(__half2*)&v.w);
    a[0] += f0.x; a[1] += f0.y;
    a[2] += f1.x; a[3] += f1.y;
    a[4] += f2.x; a[5] += f2.y;
    a[6] += f3.x; a[7] += f3.y;
}

// ---------------------------------------------------------------------------
// fused layer kernel: warp-specialized gather + GEMM
//   out = relu( agg(xh) @ Wl^T + b + xh @ Wr^T )
// 512 thr: warps 0-7 consumers (MMA, 4m x 2n over 128x128 tile),
//          warps 8-15 producers (gather agg rows -> smem A-stages).
// Ring: 2 tile-slots (each = 2 x 16KB chunk-stages), mbarrier full/empty.
// Consumer chunk order per tile: agg(0,1) then x(2,3) — preserves numerics.
// ---------------------------------------------------------------------------
extern __shared__ __align__(1024) char dsm[];

__global__ __launch_bounds__(512) void fused_layer_kernel(
    const __half* __restrict__ xh,
    const __half* __restrict__ whl,
    const __half* __restrict__ whr,
    const float* __restrict__ bias,
    float* __restrict__ outf,
    __half* __restrict__ outh) {
    __shared__ __align__(8) uint64_t s_mbar[4];   // full0,full1,empty0,empty1

    const int tid  = threadIdx.x;
    const int warp = tid >> 5;
    const int lane = tid & 31;
    const uint32_t sbase = smem_u32(dsm);
    const uint32_t mb_full0  = smem_u32(&s_mbar[0]);
    const uint32_t mb_full1  = smem_u32(&s_mbar[1]);
    const uint32_t mb_empty0 = smem_u32(&s_mbar[2]);
    const uint32_t mb_empty1 = smem_u32(&s_mbar[3]);

    if (tid == 0) {
        mbar_init(mb_full0, 256);
        mbar_init(mb_full1, 256);
        mbar_init(mb_empty0, 256);
        mbar_init(mb_empty1, 256);
    }
    __syncthreads();

    if (warp < 8) {
        // =================== CONSUMER ===================
        const int wm = warp & 3;
        const int wn = warp >> 2;
        const int r8 = lane & 7;
        const int sel = lane >> 3;
        const int g = lane >> 2, t = lane & 3;

        // B resident: 4 chunks x 16 KB
#pragma unroll
        for (int r = 0; r < 16; r++) {
            int idx = tid + (r << 8);       // 0..4095
            int kc  = idx >> 10;
            int rem = idx & 1023;
            int n   = rem >> 3;
            int q   = rem & 7;
            const __half* Wsrc = (kc < 2) ? whl : whr;
            int ko = (kc & 1) << 6;
            uint32_t dst = sbase + SB_B + kc * 16384 + n * 128 +
                           ((q << 4) ^ ((n & 7) << 4));
            cp16(dst, Wsrc + n * HIDDEN + ko + (q << 3), 16u);
        }
        asm volatile("cp.async.commit_group;" ::: "memory");

        float bb0[8], bb1[8];
#pragma unroll
        for (int j = 0; j < 8; j++) {
            int col = (wn << 6) + (j << 3) + (t << 1);
            bb0[j] = __ldg(bias + col);
            bb1[j] = __ldg(bias + col + 1);
        }

        // flat x-chunk issue stream (chunks 2,3 of each tile)
        int ptile = blockIdx.x, pxc = 0, sstep = 0;
        auto issue_x = [&]() {
            if (ptile < GEMM_TILES) {
                const int m0 = ptile * 128;
                const int ko = (pxc & 1) << 6;   // chunk2->0, chunk3->64
                const uint32_t sb = sbase + SB_X + (sstep & 1) * 16384;
#pragma unroll
                for (int r = 0; r < 4; r++) {
                    int idx = tid + (r << 8);    // 0..1023
                    int row = idx >> 3;
                    int q   = idx & 7;
                    int grow = m0 + row;
                    uint32_t dst = sb + row * 128 + ((q << 4) ^ ((row & 7) << 4));
                    cp16(dst, xh + (size_t)grow * HIDDEN + ko + (q << 3),
                         (grow < N_NODES) ? 16u : 0u);
                }
                if (++pxc == 2) { pxc = 0; ptile += FUSE_NBLK; }
            }
            asm volatile("cp.async.commit_group;" ::: "memory");
            sstep++;
        };
        issue_x();
        issue_x();

        float acc[2][8][4];
        auto mma_chunk = [&](uint32_t sA, uint32_t sB) {
#pragma unroll
            for (int sg = 0; sg < 4; sg++) {
                uint32_t kA = (uint32_t)((((sel >> 1) << 4) | (sg << 5)) ^ (r8 << 4));
                uint32_t af[2][4];
#pragma unroll
                for (int i = 0; i < 2; i++) {
                    int mt = (wm << 1) + i;
                    int rowA = mt * 16 + ((sel & 1) << 3) + r8;
                    ldsm_x4(af[i], sA + rowA * 128 + kA);
                }
                uint32_t kB = (uint32_t)((((sel & 1) << 4) | (sg << 5)) ^ (r8 << 4));
#pragma unroll
                for (int jp = 0; jp < 4; jp++) {
                    int nB = (wn << 6) + jp * 16 + (((sel >> 1) & 1) << 3) + r8;
                    uint32_t bf[4];
                    ldsm_x4(bf, sB + nB * 128 + kB);
#pragma unroll
                    for (int i = 0; i < 2; i++) {
                        mma_f16(acc[i][2 * jp],     af[i][0], af[i][1],
                                af[i][2], af[i][3], bf[0], bf[1]);
                        mma_f16(acc[i][2 * jp + 1], af[i][0], af[i][1],
                                af[i][2], af[i][3], bf[2], bf[3]);
                    }
                }
            }
        };

        int tl = 0, cstep = 0;
        for (int tile = blockIdx.x; tile < GEMM_TILES; tile += FUSE_NBLK, tl++) {
            const int m0 = tile * 128;
            const int slot = tl & 1;
            const uint32_t fphase = (uint32_t)((tl >> 1) & 1);

#pragma unroll
            for (int i = 0; i < 2; i++)
#pragma unroll
                for (int j = 0; j < 8; j++)
#pragma unroll
                    for (int r = 0; r < 4; r++) acc[i][j][r] = 0.f;

            // agg chunks (0,1) from producer stages
            mbar_wait(slot ? mb_full1 : mb_full0, fphase);
#pragma unroll
            for (int c = 0; c < 2; c++) {
                mma_chunk(sbase + SB_AGG + (2 * slot + c) * 16384,
                          sbase + SB_B + c * 16384);
            }
            mbar_arrive(slot ? mb_empty1 : mb_empty0);

            // x chunks (2,3) from cp.async stages
#pragma unroll
            for (int c = 2; c < 4; c++) {
                asm volatile("cp.async.wait_group 1;" ::: "memory");
                asm volatile("bar.sync 1, 256;" ::: "memory");
                mma_chunk(sbase + SB_X + (cstep & 1) * 16384,
                          sbase + SB_B + c * 16384);
                cstep++;
                asm volatile("bar.sync 1, 256;" ::: "memory");
                issue_x();
            }

            // epilogue: bias + relu
#pragma unroll
            for (int i = 0; i < 2; i++) {
                int rbase = m0 + (wm << 5) + (i << 4) + g;
#pragma unroll
                for (int j = 0; j < 8; j++) {
                    int col = (wn << 6) + (j << 3) + (t << 1);
                    float v00 = fmaxf(acc[i][j][0] + bb0[j], 0.f);
                    float v01 = fmaxf(acc[i][j][1] + bb1[j], 0.f);
                    float v10 = fmaxf(acc[i][j][2] + bb0[j], 0.f);
                    float v11 = fmaxf(acc[i][j][3] + bb1[j], 0.f);
                    if (outh) {
                        if (rbase < N_NODES) {
                            __half2 h = __float22half2_rn(make_float2(v00, v01));
                            *(uint32_t*)(outh + (size_t)rbase * HIDDEN + col) =
                                *(uint32_t*)&h;
                        }
                        if (rbase + 8 < N_NODES) {
                            __half2 h = __float22half2_rn(make_float2(v10, v11));
                            *(uint32_t*)(outh + (size_t)(rbase + 8) * HIDDEN + col) =
                                *(uint32_t*)&h;
                        }
                    } else {
                        if (rbase < N_NODES)
                            *(float2*)(outf + (size_t)rbase * HIDDEN + col) =
                                make_float2(v00, v01);
                        if (rbase + 8 < N_NODES)
                            *(float2*)(outf + (size_t)(rbase + 8) * HIDDEN + col) =
                                make_float2(v10, v11);
                    }
                }
            }
        }
    } else {
        // =================== PRODUCER ===================
        const int pw  = warp - 8;             // 0..7 -> 16 rows each
        const int sub = lane >> 4;
        const int lc  = (lane & 15) << 3;     // half-index in 128-col row
        const int chunkSel = (lane >> 3) & 1; // 0: cols 0-63, 1: cols 64-127
        const int q = lane & 7;

        int tl = 0;
        for (int tile = blockIdx.x; tile < GEMM_TILES; tile += FUSE_NBLK, tl++) {
            const int slot = tl & 1;
            const uint32_t ephase = (uint32_t)(1 ^ ((tl >> 1) & 1));
            mbar_wait(slot ? mb_empty1 : mb_empty0, ephase);

            const uint32_t stage0 = sbase + SB_AGG + (2 * slot) * 16384;
#pragma unroll 1
            for (int i = 0; i < 16; i++) {
                const int row = pw * 16 + i;
                const int node = tile * 128 + row;
                uint32_t dst = stage0 + chunkSel * 16384 + row * 128 +
                               ((q << 4) ^ ((row & 7) << 4));
                if (node < N_NODES) {
                    const int deg = g_cnt[node];
                    const int beg = node * CAP;
                    const int end = beg + deg;
                    float invd = 1.0f / fmaxf((float)deg, 1.0f);
                    float acc[8];
#pragma unroll
                    for (int u = 0; u < 8; u++) acc[u] = 0.f;
                    int e = beg;
                    for (; e + 16 <= end; e += 16) {
                        int sidx[8];
#pragma unroll
                        for (int u = 0; u < 8; u++)
                            sidx[u] = __ldg(&g_col[e + 2 * u + sub]);
                        uint4 v[8];
#pragma unroll
                        for (int u = 0; u < 8; u++)
                            v[u] = *(const uint4*)(xh + (size_t)sidx[u] * HIDDEN + lc);
#pragma unroll
                        for (int u = 0; u < 8; u++) acc8(acc, v[u]);
                    }
                    for (; e + 2 <= end; e += 2) {
                        int s0 = __ldg(&g_col[e + sub]);
                        uint4 v0 = *(const uint4*)(xh + (size_t)s0 * HIDDEN + lc);
                        acc8(acc, v0);
                    }
                    if (e < end && sub == 0) {
                        int s0 = __ldg(&g_col[e]);
                        uint4 v0 = *(const uint4*)(xh + (size_t)s0 * HIDDEN + lc);
                        acc8(acc, v0);
                    }
#pragma unroll
                    for (int u = 0; u < 8; u++) {
                        acc[u] += __shfl_xor_sync(0xffffffffu, acc[u], 16);
                        acc[u] *= invd;
                    }
                    if (sub == 0) {
                        __half2 h0 = __float22half2_rn(make_float2(acc[0], acc[1]));
                        __half2 h1 = __float22half2_rn(make_float2(acc[2], acc[3]));
                        __half2 h2 = __float22half2_rn(make_float2(acc[4], acc[5]));
                        __half2 h3 = __float22half2_rn(make_float2(acc[6], acc[7]));
                        uint4 st;
                        st.x = *(uint32_t*)&h0;
                        st.y = *(uint32_t*)&h1;
                        st.z = *(uint32_t*)&h2;
                        st.w = *(uint32_t*)&h3;
                        *(uint4*)(dsm + (dst - sbase)) = st;
                    }
                } else if (sub == 0) {
                    *(uint4*)(dsm + (dst - sbase)) = make_uint4(0, 0, 0, 0);
                }
            }
            mbar_arrive(slot ? mb_full1 : mb_full0);
        }
    }
}

// ---------------------------------------------------------------------------
// launch
// ---------------------------------------------------------------------------
extern "C" void kernel_launch(void* const* d_in, const int* in_sizes, int n_in,
                              void* d_out, int out_size) {
    const float* ue = (const float*)d_in[0];
    const float* ie = (const float*)d_in[1];
    const float* Wl = (const float*)d_in[2];
    const float* bl = (const float*)d_in[3];
    const float* Wr = (const float*)d_in[4];
    const int*   ei = (const int*)d_in[5];
    float* out = (float*)d_out;

    __half *pxh0, *pxh1, *pwh;
    cudaGetSymbolAddress((void**)&pxh0, g_xh0);
    cudaGetSymbolAddress((void**)&pxh1, g_xh1);
    cudaGetSymbolAddress((void**)&pwh, g_wh);

    cudaFuncSetAttribute(fused_layer_kernel,
                         cudaFuncAttributeMaxDynamicSharedMemorySize,
                         FUSE_SMEM);

    const int T = 256;

    zero_cnt_kernel<<<ZC_BLOCKS, T>>>();
    fat_prologue_kernel<<<CVX_BLOCKS + CVW_BLOCKS + F4_BLOCKS, T>>>(
        ue, ie, Wl, Wr, ei);

    const int HH = HIDDEN * HIDDEN;
    // layer 0
    fused_layer_kernel<<<FUSE_NBLK, 512, FUSE_SMEM>>>(
        pxh0, pwh, pwh + 2 * HH, bl, nullptr, pxh1);
    // layer 1
    fused_layer_kernel<<<FUSE_NBLK, 512, FUSE_SMEM>>>(
        pxh1, pwh + HH, pwh + 3 * HH, bl + HIDDEN, out, nullptr);
}